// round 7
// baseline (speedup 1.0000x reference)
#include <cuda_runtime.h>
#include <cuda_bf16.h>
#include <math.h>

#define BATCH    2
#define SEQ      2048
#define D_MODEL  1024
#define N_HEADS  16
#define HEAD_DIM 64
#define M_TOTAL  (BATCH * SEQ)          // 4096
#define QKV_ELEMS (BATCH * N_HEADS * SEQ * HEAD_DIM)   // 4,194,304
#define KTILE 32

// -------- device scratch (no allocations allowed) --------
__device__ float g_q[QKV_ELEMS];
__device__ float g_k[QKV_ELEMS];
__device__ float g_v[QKV_ELEMS];
__device__ float g_attn[M_TOTAL * D_MODEL];   // [b*S + s][h*64 + e]

// ============================================================
// Kernel 1: fused QKV projection.
// out[b][h][s][e] = sum_d X[b][s][d] * W[h][d][e] + bias[h][e]
// GEMM view: M = B*S = 4096, N = H*hd = 1024, K = D = 1024.
// grid = (N/128, M/128, 3), block = 256 threads, 8x8 micro-tile.
// K-tile = 32, register-prefetch double buffering.
// ============================================================
__global__ __launch_bounds__(256)
void qkv_kernel(const float* __restrict__ X,
                const float* __restrict__ Wq, const float* __restrict__ Wk,
                const float* __restrict__ Wv,
                const float* __restrict__ bq, const float* __restrict__ bk,
                const float* __restrict__ bv)
{
    const int which = blockIdx.z;
    const float* __restrict__ W    = (which == 0) ? Wq : (which == 1) ? Wk : Wv;
    const float* __restrict__ bias = (which == 0) ? bq : (which == 1) ? bk : bv;
    float* __restrict__ out        = (which == 0) ? g_q : (which == 1) ? g_k : g_v;

    const int n0 = blockIdx.x * 128;
    const int m0 = blockIdx.y * 128;

    __shared__ float As[KTILE][132];   // A^T : As[k][m], padded
    __shared__ float Bs[KTILE][132];   // Bs[k][n], padded

    const int tid = threadIdx.x;
    const int tx  = tid & 15;       // 16 col-groups
    const int ty  = tid >> 4;       // 16 row-groups

    float acc[8][8];
    #pragma unroll
    for (int r = 0; r < 8; r++)
        #pragma unroll
        for (int c = 0; c < 8; c++) acc[r][c] = 0.f;

    // Per-iteration load indices (A: 128x32 tile = 1024 float4; 4/thread)
    float4 a_pre[4], b_pre[4];

    // ---- prefetch first tile (k0 = 0) ----
    #pragma unroll
    for (int i = 0; i < 4; i++) {
        int f4 = tid + i * 256;
        int m  = f4 >> 3;
        int kk = (f4 & 7) * 4;
        a_pre[i] = *(const float4*)(X + (size_t)(m0 + m) * D_MODEL + kk);
        int kb = f4 >> 5;
        int n  = (f4 & 31) * 4;
        int gn = n0 + n;
        int h  = gn >> 6, e = gn & 63;
        b_pre[i] = *(const float4*)(W + ((size_t)h * D_MODEL + kb) * HEAD_DIM + e);
    }

    for (int k0 = 0; k0 < D_MODEL; k0 += KTILE) {
        // store prefetched tile into smem
        #pragma unroll
        for (int i = 0; i < 4; i++) {
            int f4 = tid + i * 256;
            int m  = f4 >> 3;
            int kk = (f4 & 7) * 4;
            As[kk + 0][m] = a_pre[i].x; As[kk + 1][m] = a_pre[i].y;
            As[kk + 2][m] = a_pre[i].z; As[kk + 3][m] = a_pre[i].w;
            int kb = f4 >> 5;
            int n  = (f4 & 31) * 4;
            *(float4*)&Bs[kb][n] = b_pre[i];
        }
        __syncthreads();

        // prefetch next tile into registers (overlaps with compute below)
        if (k0 + KTILE < D_MODEL) {
            int k1 = k0 + KTILE;
            #pragma unroll
            for (int i = 0; i < 4; i++) {
                int f4 = tid + i * 256;
                int m  = f4 >> 3;
                int kk = (f4 & 7) * 4;
                a_pre[i] = *(const float4*)(X + (size_t)(m0 + m) * D_MODEL + k1 + kk);
                int kb = f4 >> 5;
                int n  = (f4 & 31) * 4;
                int gn = n0 + n;
                int h  = gn >> 6, e = gn & 63;
                b_pre[i] = *(const float4*)(W + ((size_t)h * D_MODEL + (k1 + kb)) * HEAD_DIM + e);
            }
        }

        #pragma unroll
        for (int kk = 0; kk < KTILE; kk++) {
            float4 a0 = *(const float4*)&As[kk][ty * 4];
            float4 a1 = *(const float4*)&As[kk][64 + ty * 4];
            float4 b0 = *(const float4*)&Bs[kk][tx * 4];
            float4 b1 = *(const float4*)&Bs[kk][64 + tx * 4];
            float a[8] = {a0.x, a0.y, a0.z, a0.w, a1.x, a1.y, a1.z, a1.w};
            float bb[8] = {b0.x, b0.y, b0.z, b0.w, b1.x, b1.y, b1.z, b1.w};
            #pragma unroll
            for (int r = 0; r < 8; r++)
                #pragma unroll
                for (int c = 0; c < 8; c++)
                    acc[r][c] = fmaf(a[r], bb[c], acc[r][c]);
        }
        __syncthreads();
    }

    // Epilogue: scatter to [b][h][s][e] with bias
    #pragma unroll
    for (int r = 0; r < 8; r++) {
        int mloc = (r < 4) ? (ty * 4 + r) : (64 + ty * 4 + (r - 4));
        int m = m0 + mloc;
        int b = m >> 11;            // / SEQ
        int s = m & (SEQ - 1);
        #pragma unroll
        for (int cg = 0; cg < 2; cg++) {
            int n = n0 + cg * 64 + tx * 4;
            int h = n >> 6, e = n & 63;
            float4 o;
            o.x = acc[r][cg * 4 + 0] + __ldg(&bias[h * HEAD_DIM + e + 0]);
            o.y = acc[r][cg * 4 + 1] + __ldg(&bias[h * HEAD_DIM + e + 1]);
            o.z = acc[r][cg * 4 + 2] + __ldg(&bias[h * HEAD_DIM + e + 2]);
            o.w = acc[r][cg * 4 + 3] + __ldg(&bias[h * HEAD_DIM + e + 3]);
            *(float4*)(out + ((size_t)(b * N_HEADS + h) * SEQ + s) * HEAD_DIM + e) = o;
        }
    }
}

// ============================================================
// Kernel 2: causal flash attention (online softmax).
// One q-row per thread, 128 rows per block. K/V staged in smem.
// grid = (SEQ/128, B*H), block = 128.
// ============================================================
#define KT 32
__global__ __launch_bounds__(128)
void attn_kernel()
{
    const int bh   = blockIdx.y;                  // b*H + h
    const int b    = bh / N_HEADS;
    const int h    = bh % N_HEADS;
    const int row0 = blockIdx.x * 128;
    const int tid  = threadIdx.x;
    const int row  = row0 + tid;

    __shared__ float Ks[KT][HEAD_DIM];
    __shared__ float Vs[KT][HEAD_DIM];

    const float* __restrict__ qbase = g_q + (size_t)bh * SEQ * HEAD_DIM;
    const float* __restrict__ kbase = g_k + (size_t)bh * SEQ * HEAD_DIM;
    const float* __restrict__ vbase = g_v + (size_t)bh * SEQ * HEAD_DIM;

    // q row -> registers
    float q[HEAD_DIM];
    {
        const float4* qr = (const float4*)(qbase + (size_t)row * HEAD_DIM);
        #pragma unroll
        for (int i = 0; i < 16; i++) {
            float4 v = __ldg(qr + i);
            q[4 * i + 0] = v.x; q[4 * i + 1] = v.y;
            q[4 * i + 2] = v.z; q[4 * i + 3] = v.w;
        }
    }

    float o[HEAD_DIM];
    #pragma unroll
    for (int d = 0; d < HEAD_DIM; d++) o[d] = 0.f;
    float mrun = -1e30f, l = 0.f;

    const float scale = 0.125f;                    // 1/sqrt(64)
    const int ntiles  = (row0 + 128) / KT;         // causal bound for this block

    for (int t = 0; t < ntiles; t++) {
        const int kv0 = t * KT;
        // Coalesced K/V tile loads (KT x 64)
        #pragma unroll
        for (int i = 0; i < 4; i++) {
            int f4 = tid + i * 128;
            int r  = f4 >> 4;
            int d  = (f4 & 15) * 4;
            *(float4*)&Ks[r][d] = *(const float4*)(kbase + (size_t)(kv0 + r) * HEAD_DIM + d);
            *(float4*)&Vs[r][d] = *(const float4*)(vbase + (size_t)(kv0 + r) * HEAD_DIM + d);
        }
        __syncthreads();

        if (kv0 <= row) {   // this tile contributes to this row
            float sc[KT];
            float tmax = mrun;
            #pragma unroll
            for (int j = 0; j < KT; j++) {
                int kv = kv0 + j;
                float s;
                if (kv <= row) {
                    float s0 = 0.f, s1 = 0.f, s2 = 0.f, s3 = 0.f;
                    #pragma unroll
                    for (int dd = 0; dd < 16; dd++) {
                        float4 kk4 = *(const float4*)&Ks[j][dd * 4];
                        s0 = fmaf(q[4 * dd + 0], kk4.x, s0);
                        s1 = fmaf(q[4 * dd + 1], kk4.y, s1);
                        s2 = fmaf(q[4 * dd + 2], kk4.z, s2);
                        s3 = fmaf(q[4 * dd + 3], kk4.w, s3);
                    }
                    s = ((s0 + s1) + (s2 + s3)) * scale;
                } else {
                    s = -1e30f;
                }
                sc[j] = s;
                tmax = fmaxf(tmax, s);
            }

            float corr = __expf(mrun - tmax);
            mrun = tmax;
            l *= corr;
            #pragma unroll
            for (int d = 0; d < HEAD_DIM; d++) o[d] *= corr;

            #pragma unroll
            for (int j = 0; j < KT; j++) {
                float p = __expf(sc[j] - mrun);
                l += p;
                #pragma unroll
                for (int dd = 0; dd < 16; dd++) {
                    float4 vv = *(const float4*)&Vs[j][dd * 4];
                    o[4 * dd + 0] = fmaf(p, vv.x, o[4 * dd + 0]);
                    o[4 * dd + 1] = fmaf(p, vv.y, o[4 * dd + 1]);
                    o[4 * dd + 2] = fmaf(p, vv.z, o[4 * dd + 2]);
                    o[4 * dd + 3] = fmaf(p, vv.w, o[4 * dd + 3]);
                }
            }
        }
        __syncthreads();
    }

    // Normalize + write to concat layout [b][s][h*64 + e]
    float inv = 1.f / l;
    float* outp = g_attn + ((size_t)b * SEQ + row) * D_MODEL + h * HEAD_DIM;
    #pragma unroll
    for (int dd = 0; dd < 16; dd++) {
        float4 v;
        v.x = o[4 * dd + 0] * inv; v.y = o[4 * dd + 1] * inv;
        v.z = o[4 * dd + 2] * inv; v.w = o[4 * dd + 3] * inv;
        *(float4*)(outp + 4 * dd) = v;
    }
}

// ============================================================
// Kernel 3: output projection.
// out[m][n] = sum_k g_attn[m][k] * Wo[k][n] + bo[n]
// M = 4096, N = 1024, K = 1024. grid = (8, 32), block = 256.
// K-tile = 32, register-prefetch double buffering.
// ============================================================
__global__ __launch_bounds__(256)
void oproj_kernel(const float* __restrict__ Wo, const float* __restrict__ bo,
                  float* __restrict__ out)
{
    const int n0 = blockIdx.x * 128;
    const int m0 = blockIdx.y * 128;

    __shared__ float As[KTILE][132];
    __shared__ float Bs[KTILE][132];

    const int tid = threadIdx.x;
    const int tx  = tid & 15;
    const int ty  = tid >> 4;

    float acc[8][8];
    #pragma unroll
    for (int r = 0; r < 8; r++)
        #pragma unroll
        for (int c = 0; c < 8; c++) acc[r][c] = 0.f;

    float4 a_pre[4], b_pre[4];
    #pragma unroll
    for (int i = 0; i < 4; i++) {
        int f4 = tid + i * 256;
        int m  = f4 >> 3;
        int kk = (f4 & 7) * 4;
        a_pre[i] = *(const float4*)(g_attn + (size_t)(m0 + m) * D_MODEL + kk);
        int kb = f4 >> 5;
        int n  = (f4 & 31) * 4;
        b_pre[i] = *(const float4*)(Wo + (size_t)kb * D_MODEL + n0 + n);
    }

    for (int k0 = 0; k0 < D_MODEL; k0 += KTILE) {
        #pragma unroll
        for (int i = 0; i < 4; i++) {
            int f4 = tid + i * 256;
            int m  = f4 >> 3;
            int kk = (f4 & 7) * 4;
            As[kk + 0][m] = a_pre[i].x; As[kk + 1][m] = a_pre[i].y;
            As[kk + 2][m] = a_pre[i].z; As[kk + 3][m] = a_pre[i].w;
            int kb = f4 >> 5;
            int n  = (f4 & 31) * 4;
            *(float4*)&Bs[kb][n] = b_pre[i];
        }
        __syncthreads();

        if (k0 + KTILE < D_MODEL) {
            int k1 = k0 + KTILE;
            #pragma unroll
            for (int i = 0; i < 4; i++) {
                int f4 = tid + i * 256;
                int m  = f4 >> 3;
                int kk = (f4 & 7) * 4;
                a_pre[i] = *(const float4*)(g_attn + (size_t)(m0 + m) * D_MODEL + k1 + kk);
                int kb = f4 >> 5;
                int n  = (f4 & 31) * 4;
                b_pre[i] = *(const float4*)(Wo + (size_t)(k1 + kb) * D_MODEL + n0 + n);
            }
        }

        #pragma unroll
        for (int kk = 0; kk < KTILE; kk++) {
            float4 a0 = *(const float4*)&As[kk][ty * 4];
            float4 a1 = *(const float4*)&As[kk][64 + ty * 4];
            float4 b0 = *(const float4*)&Bs[kk][tx * 4];
            float4 b1 = *(const float4*)&Bs[kk][64 + tx * 4];
            float a[8] = {a0.x, a0.y, a0.z, a0.w, a1.x, a1.y, a1.z, a1.w};
            float bb[8] = {b0.x, b0.y, b0.z, b0.w, b1.x, b1.y, b1.z, b1.w};
            #pragma unroll
            for (int r = 0; r < 8; r++)
                #pragma unroll
                for (int c = 0; c < 8; c++)
                    acc[r][c] = fmaf(a[r], bb[c], acc[r][c]);
        }
        __syncthreads();
    }

    #pragma unroll
    for (int r = 0; r < 8; r++) {
        int mloc = (r < 4) ? (ty * 4 + r) : (64 + ty * 4 + (r - 4));
        int m = m0 + mloc;
        #pragma unroll
        for (int cg = 0; cg < 2; cg++) {
            int n = n0 + cg * 64 + tx * 4;
            float4 o;
            o.x = acc[r][cg * 4 + 0] + __ldg(&bo[n + 0]);
            o.y = acc[r][cg * 4 + 1] + __ldg(&bo[n + 1]);
            o.z = acc[r][cg * 4 + 2] + __ldg(&bo[n + 2]);
            o.w = acc[r][cg * 4 + 3] + __ldg(&bo[n + 3]);
            *(float4*)(out + (size_t)m * D_MODEL + n) = o;
        }
    }
}

// ============================================================
extern "C" void kernel_launch(void* const* d_in, const int* in_sizes, int n_in,
                              void* d_out, int out_size)
{
    const float* X  = (const float*)d_in[0];
    const float* Wq = (const float*)d_in[1];
    const float* Wk = (const float*)d_in[2];
    const float* Wv = (const float*)d_in[3];
    const float* bq = (const float*)d_in[4];
    const float* bk = (const float*)d_in[5];
    const float* bv = (const float*)d_in[6];
    const float* Wo = (const float*)d_in[7];
    const float* bo = (const float*)d_in[8];
    float* out = (float*)d_out;

    qkv_kernel<<<dim3(D_MODEL / 128, M_TOTAL / 128, 3), 256>>>(X, Wq, Wk, Wv, bq, bk, bv);
    attn_kernel<<<dim3(SEQ / 128, BATCH * N_HEADS), 128>>>();
    oproj_kernel<<<dim3(D_MODEL / 128, M_TOTAL / 128), 256>>>(Wo, bo, out);
}

// round 10
// speedup vs baseline: 1.3633x; 1.3633x over previous
#include <cuda_runtime.h>
#include <cuda_bf16.h>
#include <math.h>
#include <stdint.h>

#define BATCH    2
#define SEQ      2048
#define D_MODEL  1024
#define N_HEADS  16
#define HEAD_DIM 64
#define M_TOTAL  (BATCH * SEQ)          // 4096
#define QKV_ELEMS (BATCH * N_HEADS * SEQ * HEAD_DIM)   // 4,194,304
#define KTILE 32

// -------- device scratch (no allocations allowed) --------
__device__ float g_q[QKV_ELEMS];
__device__ float g_k[QKV_ELEMS];
__device__ float g_v[QKV_ELEMS];
__device__ float g_attn[M_TOTAL * D_MODEL];   // [b*S + s][h*64 + e]

// ---------- tf32 mma helpers ----------
__device__ __forceinline__ uint32_t f2tf32(float x) {
    uint32_t r;
    asm("cvt.rna.tf32.f32 %0, %1;" : "=r"(r) : "f"(x));
    return r;
}

__device__ __forceinline__ void mma_tf32(float* c, const uint32_t* a, const uint32_t* b) {
    asm volatile(
        "mma.sync.aligned.m16n8k8.row.col.f32.tf32.tf32.f32 "
        "{%0,%1,%2,%3}, {%4,%5,%6,%7}, {%8,%9}, {%0,%1,%2,%3};"
        : "+f"(c[0]), "+f"(c[1]), "+f"(c[2]), "+f"(c[3])
        : "r"(a[0]), "r"(a[1]), "r"(a[2]), "r"(a[3]), "r"(b[0]), "r"(b[1]));
}

#define AS_STRIDE 36    // floats per A row (32 + 4 pad)
#define BS_STRIDE 136   // floats per B row (128 + 8 pad)

// ============================================================
// Kernel 1: fused QKV projection, tf32 tensor cores.
// GEMM: M=4096, N=1024, K=1024. Block tile 128x128x32.
// 8 warps in 2x4; warp tile 64x32 = 4x4 m16n8k8 mma.
// grid = (8, 32, 3), block = 256.
// ============================================================
__global__ __launch_bounds__(256)
void qkv_kernel(const float* __restrict__ X,
                const float* __restrict__ Wq, const float* __restrict__ Wk,
                const float* __restrict__ Wv,
                const float* __restrict__ bq, const float* __restrict__ bk,
                const float* __restrict__ bv)
{
    const int which = blockIdx.z;
    const float* __restrict__ W    = (which == 0) ? Wq : (which == 1) ? Wk : Wv;
    const float* __restrict__ bias = (which == 0) ? bq : (which == 1) ? bk : bv;
    float* __restrict__ out        = (which == 0) ? g_q : (which == 1) ? g_k : g_v;

    const int n0 = blockIdx.x * 128;
    const int m0 = blockIdx.y * 128;

    __shared__ uint32_t AsU[128 * AS_STRIDE];   // A[m][k], tf32 bits
    __shared__ uint32_t BsU[KTILE * BS_STRIDE]; // B[k][n], tf32 bits

    const int tid    = threadIdx.x;
    const int wid    = tid >> 5;
    const int lane   = tid & 31;
    const int gid    = lane >> 2;     // 0..7
    const int tig    = lane & 3;      // 0..3
    const int warp_m = wid >> 2;      // 0..1
    const int warp_n = wid & 3;       // 0..3

    float acc[4][4][4];
    #pragma unroll
    for (int mt = 0; mt < 4; mt++)
        #pragma unroll
        for (int nt = 0; nt < 4; nt++)
            #pragma unroll
            for (int i = 0; i < 4; i++) acc[mt][nt][i] = 0.f;

    float4 a_pre[4], b_pre[4];

    // ---- prefetch first tile (k0 = 0) ----
    #pragma unroll
    for (int i = 0; i < 4; i++) {
        int f4 = tid + i * 256;
        int m  = f4 >> 3;
        int kk = (f4 & 7) * 4;
        a_pre[i] = *(const float4*)(X + (size_t)(m0 + m) * D_MODEL + kk);
        int kb = f4 >> 5;
        int n  = (f4 & 31) * 4;
        int gn = n0 + n;
        int h  = gn >> 6, e = gn & 63;
        b_pre[i] = *(const float4*)(W + ((size_t)h * D_MODEL + kb) * HEAD_DIM + e);
    }

    for (int k0 = 0; k0 < D_MODEL; k0 += KTILE) {
        // store prefetched tile into smem (with tf32 conversion)
        #pragma unroll
        for (int i = 0; i < 4; i++) {
            int f4 = tid + i * 256;
            int m  = f4 >> 3;
            int kk = (f4 & 7) * 4;
            uint4 av;
            av.x = f2tf32(a_pre[i].x); av.y = f2tf32(a_pre[i].y);
            av.z = f2tf32(a_pre[i].z); av.w = f2tf32(a_pre[i].w);
            *(uint4*)&AsU[m * AS_STRIDE + kk] = av;
            int kb = f4 >> 5;
            int n  = (f4 & 31) * 4;
            uint4 bv;
            bv.x = f2tf32(b_pre[i].x); bv.y = f2tf32(b_pre[i].y);
            bv.z = f2tf32(b_pre[i].z); bv.w = f2tf32(b_pre[i].w);
            *(uint4*)&BsU[kb * BS_STRIDE + n] = bv;
        }
        __syncthreads();

        // prefetch next tile (overlaps compute)
        if (k0 + KTILE < D_MODEL) {
            int k1 = k0 + KTILE;
            #pragma unroll
            for (int i = 0; i < 4; i++) {
                int f4 = tid + i * 256;
                int m  = f4 >> 3;
                int kk = (f4 & 7) * 4;
                a_pre[i] = *(const float4*)(X + (size_t)(m0 + m) * D_MODEL + k1 + kk);
                int kb = f4 >> 5;
                int n  = (f4 & 31) * 4;
                int gn = n0 + n;
                int h  = gn >> 6, e = gn & 63;
                b_pre[i] = *(const float4*)(W + ((size_t)h * D_MODEL + (k1 + kb)) * HEAD_DIM + e);
            }
        }

        #pragma unroll
        for (int ks = 0; ks < 4; ks++) {
            const int k8 = ks * 8;
            uint32_t af[4][4], bf[4][2];
            #pragma unroll
            for (int mt = 0; mt < 4; mt++) {
                int mb = warp_m * 64 + mt * 16;
                af[mt][0] = AsU[(mb + gid    ) * AS_STRIDE + k8 + tig    ];
                af[mt][1] = AsU[(mb + gid + 8) * AS_STRIDE + k8 + tig    ];
                af[mt][2] = AsU[(mb + gid    ) * AS_STRIDE + k8 + tig + 4];
                af[mt][3] = AsU[(mb + gid + 8) * AS_STRIDE + k8 + tig + 4];
            }
            #pragma unroll
            for (int nt = 0; nt < 4; nt++) {
                int nb = warp_n * 32 + nt * 8;
                bf[nt][0] = BsU[(k8 + tig    ) * BS_STRIDE + nb + gid];
                bf[nt][1] = BsU[(k8 + tig + 4) * BS_STRIDE + nb + gid];
            }
            #pragma unroll
            for (int mt = 0; mt < 4; mt++)
                #pragma unroll
                for (int nt = 0; nt < 4; nt++)
                    mma_tf32(acc[mt][nt], af[mt], bf[nt]);
        }
        __syncthreads();
    }

    // Epilogue: scatter to [b][h][s][e] with bias
    #pragma unroll
    for (int mt = 0; mt < 4; mt++) {
        #pragma unroll
        for (int nt = 0; nt < 4; nt++) {
            int col = n0 + warp_n * 32 + nt * 8 + 2 * tig;
            int h = col >> 6, e = col & 63;
            float bx = __ldg(&bias[h * HEAD_DIM + e]);
            float by = __ldg(&bias[h * HEAD_DIM + e + 1]);
            #pragma unroll
            for (int half = 0; half < 2; half++) {
                int row = m0 + warp_m * 64 + mt * 16 + gid + half * 8;
                int b = row >> 11;
                int s = row & (SEQ - 1);
                float2 v;
                v.x = acc[mt][nt][2 * half + 0] + bx;
                v.y = acc[mt][nt][2 * half + 1] + by;
                *(float2*)(out + ((size_t)(b * N_HEADS + h) * SEQ + s) * HEAD_DIM + e) = v;
            }
        }
    }
}

// ============================================================
// Kernel 2: causal flash attention (online softmax). UNCHANGED.
// grid = (SEQ/128, B*H), block = 128.
// ============================================================
#define KT 32
__global__ __launch_bounds__(128)
void attn_kernel()
{
    const int bh   = blockIdx.y;                  // b*H + h
    const int b    = bh / N_HEADS;
    const int h    = bh % N_HEADS;
    const int row0 = blockIdx.x * 128;
    const int tid  = threadIdx.x;
    const int row  = row0 + tid;

    __shared__ float Ks[KT][HEAD_DIM];
    __shared__ float Vs[KT][HEAD_DIM];

    const float* __restrict__ qbase = g_q + (size_t)bh * SEQ * HEAD_DIM;
    const float* __restrict__ kbase = g_k + (size_t)bh * SEQ * HEAD_DIM;
    const float* __restrict__ vbase = g_v + (size_t)bh * SEQ * HEAD_DIM;

    float q[HEAD_DIM];
    {
        const float4* qr = (const float4*)(qbase + (size_t)row * HEAD_DIM);
        #pragma unroll
        for (int i = 0; i < 16; i++) {
            float4 v = __ldg(qr + i);
            q[4 * i + 0] = v.x; q[4 * i + 1] = v.y;
            q[4 * i + 2] = v.z; q[4 * i + 3] = v.w;
        }
    }

    float o[HEAD_DIM];
    #pragma unroll
    for (int d = 0; d < HEAD_DIM; d++) o[d] = 0.f;
    float mrun = -1e30f, l = 0.f;

    const float scale = 0.125f;                    // 1/sqrt(64)
    const int ntiles  = (row0 + 128) / KT;

    for (int t = 0; t < ntiles; t++) {
        const int kv0 = t * KT;
        #pragma unroll
        for (int i = 0; i < 4; i++) {
            int f4 = tid + i * 128;
            int r  = f4 >> 4;
            int d  = (f4 & 15) * 4;
            *(float4*)&Ks[r][d] = *(const float4*)(kbase + (size_t)(kv0 + r) * HEAD_DIM + d);
            *(float4*)&Vs[r][d] = *(const float4*)(vbase + (size_t)(kv0 + r) * HEAD_DIM + d);
        }
        __syncthreads();

        if (kv0 <= row) {
            float sc[KT];
            float tmax = mrun;
            #pragma unroll
            for (int j = 0; j < KT; j++) {
                int kv = kv0 + j;
                float s;
                if (kv <= row) {
                    float s0 = 0.f, s1 = 0.f, s2 = 0.f, s3 = 0.f;
                    #pragma unroll
                    for (int dd = 0; dd < 16; dd++) {
                        float4 kk4 = *(const float4*)&Ks[j][dd * 4];
                        s0 = fmaf(q[4 * dd + 0], kk4.x, s0);
                        s1 = fmaf(q[4 * dd + 1], kk4.y, s1);
                        s2 = fmaf(q[4 * dd + 2], kk4.z, s2);
                        s3 = fmaf(q[4 * dd + 3], kk4.w, s3);
                    }
                    s = ((s0 + s1) + (s2 + s3)) * scale;
                } else {
                    s = -1e30f;
                }
                sc[j] = s;
                tmax = fmaxf(tmax, s);
            }

            float corr = __expf(mrun - tmax);
            mrun = tmax;
            l *= corr;
            #pragma unroll
            for (int d = 0; d < HEAD_DIM; d++) o[d] *= corr;

            #pragma unroll
            for (int j = 0; j < KT; j++) {
                float p = __expf(sc[j] - mrun);
                l += p;
                #pragma unroll
                for (int dd = 0; dd < 16; dd++) {
                    float4 vv = *(const float4*)&Vs[j][dd * 4];
                    o[4 * dd + 0] = fmaf(p, vv.x, o[4 * dd + 0]);
                    o[4 * dd + 1] = fmaf(p, vv.y, o[4 * dd + 1]);
                    o[4 * dd + 2] = fmaf(p, vv.z, o[4 * dd + 2]);
                    o[4 * dd + 3] = fmaf(p, vv.w, o[4 * dd + 3]);
                }
            }
        }
        __syncthreads();
    }

    float inv = 1.f / l;
    float* outp = g_attn + ((size_t)b * SEQ + row) * D_MODEL + h * HEAD_DIM;
    #pragma unroll
    for (int dd = 0; dd < 16; dd++) {
        float4 v;
        v.x = o[4 * dd + 0] * inv; v.y = o[4 * dd + 1] * inv;
        v.z = o[4 * dd + 2] * inv; v.w = o[4 * dd + 3] * inv;
        *(float4*)(outp + 4 * dd) = v;
    }
}

// ============================================================
// Kernel 3: output projection, tf32 tensor cores.
// out[m][n] = sum_k g_attn[m][k] * Wo[k][n] + bo[n]
// grid = (8, 32), block = 256. Same tiling as qkv.
// ============================================================
__global__ __launch_bounds__(256)
void oproj_kernel(const float* __restrict__ Wo, const float* __restrict__ bo,
                  float* __restrict__ out)
{
    const int n0 = blockIdx.x * 128;
    const int m0 = blockIdx.y * 128;

    __shared__ uint32_t AsU[128 * AS_STRIDE];
    __shared__ uint32_t BsU[KTILE * BS_STRIDE];

    const int tid    = threadIdx.x;
    const int wid    = tid >> 5;
    const int lane   = tid & 31;
    const int gid    = lane >> 2;
    const int tig    = lane & 3;
    const int warp_m = wid >> 2;
    const int warp_n = wid & 3;

    float acc[4][4][4];
    #pragma unroll
    for (int mt = 0; mt < 4; mt++)
        #pragma unroll
        for (int nt = 0; nt < 4; nt++)
            #pragma unroll
            for (int i = 0; i < 4; i++) acc[mt][nt][i] = 0.f;

    float4 a_pre[4], b_pre[4];
    #pragma unroll
    for (int i = 0; i < 4; i++) {
        int f4 = tid + i * 256;
        int m  = f4 >> 3;
        int kk = (f4 & 7) * 4;
        a_pre[i] = *(const float4*)(g_attn + (size_t)(m0 + m) * D_MODEL + kk);
        int kb = f4 >> 5;
        int n  = (f4 & 31) * 4;
        b_pre[i] = *(const float4*)(Wo + (size_t)kb * D_MODEL + n0 + n);
    }

    for (int k0 = 0; k0 < D_MODEL; k0 += KTILE) {
        #pragma unroll
        for (int i = 0; i < 4; i++) {
            int f4 = tid + i * 256;
            int m  = f4 >> 3;
            int kk = (f4 & 7) * 4;
            uint4 av;
            av.x = f2tf32(a_pre[i].x); av.y = f2tf32(a_pre[i].y);
            av.z = f2tf32(a_pre[i].z); av.w = f2tf32(a_pre[i].w);
            *(uint4*)&AsU[m * AS_STRIDE + kk] = av;
            int kb = f4 >> 5;
            int n  = (f4 & 31) * 4;
            uint4 bv;
            bv.x = f2tf32(b_pre[i].x); bv.y = f2tf32(b_pre[i].y);
            bv.z = f2tf32(b_pre[i].z); bv.w = f2tf32(b_pre[i].w);
            *(uint4*)&BsU[kb * BS_STRIDE + n] = bv;
        }
        __syncthreads();

        if (k0 + KTILE < D_MODEL) {
            int k1 = k0 + KTILE;
            #pragma unroll
            for (int i = 0; i < 4; i++) {
                int f4 = tid + i * 256;
                int m  = f4 >> 3;
                int kk = (f4 & 7) * 4;
                a_pre[i] = *(const float4*)(g_attn + (size_t)(m0 + m) * D_MODEL + k1 + kk);
                int kb = f4 >> 5;
                int n  = (f4 & 31) * 4;
                b_pre[i] = *(const float4*)(Wo + (size_t)(k1 + kb) * D_MODEL + n0 + n);
            }
        }

        #pragma unroll
        for (int ks = 0; ks < 4; ks++) {
            const int k8 = ks * 8;
            uint32_t af[4][4], bf[4][2];
            #pragma unroll
            for (int mt = 0; mt < 4; mt++) {
                int mb = warp_m * 64 + mt * 16;
                af[mt][0] = AsU[(mb + gid    ) * AS_STRIDE + k8 + tig    ];
                af[mt][1] = AsU[(mb + gid + 8) * AS_STRIDE + k8 + tig    ];
                af[mt][2] = AsU[(mb + gid    ) * AS_STRIDE + k8 + tig + 4];
                af[mt][3] = AsU[(mb + gid + 8) * AS_STRIDE + k8 + tig + 4];
            }
            #pragma unroll
            for (int nt = 0; nt < 4; nt++) {
                int nb = warp_n * 32 + nt * 8;
                bf[nt][0] = BsU[(k8 + tig    ) * BS_STRIDE + nb + gid];
                bf[nt][1] = BsU[(k8 + tig + 4) * BS_STRIDE + nb + gid];
            }
            #pragma unroll
            for (int mt = 0; mt < 4; mt++)
                #pragma unroll
                for (int nt = 0; nt < 4; nt++)
                    mma_tf32(acc[mt][nt], af[mt], bf[nt]);
        }
        __syncthreads();
    }

    #pragma unroll
    for (int mt = 0; mt < 4; mt++) {
        #pragma unroll
        for (int nt = 0; nt < 4; nt++) {
            int col = n0 + warp_n * 32 + nt * 8 + 2 * tig;
            float bx = __ldg(&bo[col]);
            float by = __ldg(&bo[col + 1]);
            #pragma unroll
            for (int half = 0; half < 2; half++) {
                int row = m0 + warp_m * 64 + mt * 16 + gid + half * 8;
                float2 v;
                v.x = acc[mt][nt][2 * half + 0] + bx;
                v.y = acc[mt][nt][2 * half + 1] + by;
                *(float2*)(out + (size_t)row * D_MODEL + col) = v;
            }
        }
    }
}

// ============================================================
extern "C" void kernel_launch(void* const* d_in, const int* in_sizes, int n_in,
                              void* d_out, int out_size)
{
    const float* X  = (const float*)d_in[0];
    const float* Wq = (const float*)d_in[1];
    const float* Wk = (const float*)d_in[2];
    const float* Wv = (const float*)d_in[3];
    const float* bq = (const float*)d_in[4];
    const float* bk = (const float*)d_in[5];
    const float* bv = (const float*)d_in[6];
    const float* Wo = (const float*)d_in[7];
    const float* bo = (const float*)d_in[8];
    float* out = (float*)d_out;

    qkv_kernel<<<dim3(D_MODEL / 128, M_TOTAL / 128, 3), 256>>>(X, Wq, Wk, Wv, bq, bk, bv);
    attn_kernel<<<dim3(SEQ / 128, BATCH * N_HEADS), 128>>>();
    oproj_kernel<<<dim3(D_MODEL / 128, M_TOTAL / 128), 256>>>(Wo, bo, out);
}